// round 3
// baseline (speedup 1.0000x reference)
#include <cuda_runtime.h>
#include <cstdint>

// ---------------------------------------------------------------------------
// Compile-time Cayley sign table for Cl(3,1,0), DIM = 16.
// Mirrors the reference Python blade_sign() exactly.
// For r=0 the product blade is always c = i ^ j and sign is +/-1.
// ---------------------------------------------------------------------------
namespace cl {

constexpr int NGEN = 4;
constexpr int DIM  = 16;
constexpr int PP   = 3;   // first 3 generators square to +1, 4th to -1

__host__ __device__ constexpr float metric_of(int b) {
    return b < PP ? 1.0f : -1.0f;
}

__host__ __device__ constexpr float blade_sign_of(int a_idx, int b_idx) {
    int result[NGEN] = {0, 0, 0, 0};
    int len = 0;
    for (int i = 0; i < NGEN; ++i)
        if ((a_idx >> i) & 1) result[len++] = i;
    float sign = 1.0f;
    for (int b = 0; b < NGEN; ++b) {
        if (!((b_idx >> b) & 1)) continue;
        int swaps = 0;
        bool removed = false;
        for (int i = len - 1; i >= 0; --i) {
            if (result[i] < b) break;
            if (result[i] == b) {
                sign *= metric_of(b);
                if (swaps & 1) sign = -sign;
                for (int k = i; k < len - 1; ++k) result[k] = result[k + 1];
                --len;
                removed = true;
                break;
            }
            ++swaps;
        }
        if (!removed) {
            if (swaps & 1) sign = -sign;
            int ins = len - swaps;
            for (int k = len; k > ins; --k) result[k] = result[k - 1];
            result[ins] = b;
            ++len;
        }
    }
    return sign;
}

struct Tables { float sign[DIM][DIM]; };

__host__ __device__ constexpr Tables make_tables() {
    Tables t{};
    for (int i = 0; i < DIM; ++i)
        for (int j = 0; j < DIM; ++j)
            t.sign[i][j] = blade_sign_of(i, j);
    return t;
}

} // namespace cl

// ---------------------------------------------------------------------------
// Persistent grid-stride kernel: one thread = one row per iteration.
//   reads  16 floats of a, 16 floats of b  (4x float4 each, evict-first)
//   does   256 FFMAs into 16 register accumulators (acc index folds: i^j)
//   writes 16 floats (4x float4, evict-first), clamped to [-1000, 1000]
// Grid sized to exact residency so warps stay resident and pipeline loads
// across iterations; pure HBM streaming, 192 MB total traffic.
// ---------------------------------------------------------------------------
__global__ void __launch_bounds__(256)
clifford_mul_kernel(const float4* __restrict__ a4,
                    const float4* __restrict__ b4,
                    float4* __restrict__ o4,
                    int n_rows) {
    constexpr cl::Tables TBL = cl::make_tables();

    const int stride = gridDim.x * blockDim.x;
    for (int row = blockIdx.x * blockDim.x + threadIdx.x; row < n_rows;
         row += stride) {
        const size_t base = (size_t)row * 4;

        float av[16], bv[16];
#pragma unroll
        for (int k = 0; k < 4; ++k) {
            float4 va = __ldcs(a4 + base + k);
            av[4 * k + 0] = va.x; av[4 * k + 1] = va.y;
            av[4 * k + 2] = va.z; av[4 * k + 3] = va.w;
        }
#pragma unroll
        for (int k = 0; k < 4; ++k) {
            float4 vb = __ldcs(b4 + base + k);
            bv[4 * k + 0] = vb.x; bv[4 * k + 1] = vb.y;
            bv[4 * k + 2] = vb.z; bv[4 * k + 3] = vb.w;
        }

        float acc[16];
#pragma unroll
        for (int c = 0; c < 16; ++c) acc[c] = 0.0f;

#pragma unroll
        for (int i = 0; i < 16; ++i) {
#pragma unroll
            for (int j = 0; j < 16; ++j) {
                // Compile-time constant sign after full unroll; negation is a
                // free FFMA operand modifier in SASS.
                if (TBL.sign[i][j] > 0.0f) {
                    acc[i ^ j] = fmaf(av[i], bv[j], acc[i ^ j]);
                } else {
                    acc[i ^ j] = fmaf(-av[i], bv[j], acc[i ^ j]);
                }
            }
        }

#pragma unroll
        for (int k = 0; k < 4; ++k) {
            float4 v;
            v.x = fminf(fmaxf(acc[4 * k + 0], -1000.0f), 1000.0f);
            v.y = fminf(fmaxf(acc[4 * k + 1], -1000.0f), 1000.0f);
            v.z = fminf(fmaxf(acc[4 * k + 2], -1000.0f), 1000.0f);
            v.w = fminf(fmaxf(acc[4 * k + 3], -1000.0f), 1000.0f);
            __stcs(o4 + base + k, v);
        }
    }
}

extern "C" void kernel_launch(void* const* d_in, const int* in_sizes, int n_in,
                              void* d_out, int out_size) {
    const float4* a = (const float4*)d_in[0];
    const float4* b = (const float4*)d_in[1];
    float4* out = (float4*)d_out;

    const int n_rows = in_sizes[0] / 16;  // 1,048,576
    const int threads = 256;

    // Size the grid to exact residency: blocks_per_sm * num_sms.
    // Host-side queries; not stream operations, so graph-capture safe.
    int dev = 0;
    cudaGetDevice(&dev);
    int sm_count = 148;
    cudaDeviceGetAttribute(&sm_count, cudaDevAttrMultiProcessorCount, dev);
    int blocks_per_sm = 4;
    cudaOccupancyMaxActiveBlocksPerMultiprocessor(
        &blocks_per_sm, clifford_mul_kernel, threads, 0);
    if (blocks_per_sm < 1) blocks_per_sm = 1;

    int blocks = blocks_per_sm * sm_count;
    const int max_blocks = (n_rows + threads - 1) / threads;
    if (blocks > max_blocks) blocks = max_blocks;

    clifford_mul_kernel<<<blocks, threads>>>(a, b, out, n_rows);
}

// round 4
// speedup vs baseline: 1.0555x; 1.0555x over previous
#include <cuda_runtime.h>
#include <cstdint>

// ---------------------------------------------------------------------------
// Compile-time Cayley sign table for Cl(3,1,0), DIM = 16.
// Mirrors the reference Python blade_sign() exactly.
// For r=0 the product blade is always c = i ^ j and sign is +/-1.
// ---------------------------------------------------------------------------
namespace cl {

constexpr int NGEN = 4;
constexpr int DIM  = 16;
constexpr int PP   = 3;   // first 3 generators square to +1, 4th to -1

__host__ __device__ constexpr float metric_of(int b) {
    return b < PP ? 1.0f : -1.0f;
}

__host__ __device__ constexpr float blade_sign_of(int a_idx, int b_idx) {
    int result[NGEN] = {0, 0, 0, 0};
    int len = 0;
    for (int i = 0; i < NGEN; ++i)
        if ((a_idx >> i) & 1) result[len++] = i;
    float sign = 1.0f;
    for (int b = 0; b < NGEN; ++b) {
        if (!((b_idx >> b) & 1)) continue;
        int swaps = 0;
        bool removed = false;
        for (int i = len - 1; i >= 0; --i) {
            if (result[i] < b) break;
            if (result[i] == b) {
                sign *= metric_of(b);
                if (swaps & 1) sign = -sign;
                for (int k = i; k < len - 1; ++k) result[k] = result[k + 1];
                --len;
                removed = true;
                break;
            }
            ++swaps;
        }
        if (!removed) {
            if (swaps & 1) sign = -sign;
            int ins = len - swaps;
            for (int k = len; k > ins; --k) result[k] = result[k - 1];
            result[ins] = b;
            ++len;
        }
    }
    return sign;
}

struct Tables { float sign[DIM][DIM]; };

__host__ __device__ constexpr Tables make_tables() {
    Tables t{};
    for (int i = 0; i < DIM; ++i)
        for (int j = 0; j < DIM; ++j)
            t.sign[i][j] = blade_sign_of(i, j);
    return t;
}

} // namespace cl

// ---------------------------------------------------------------------------
// Smem-staged kernel: block of 256 threads handles 256 rows.
//   Phase 1: fully-coalesced float4 global loads of a,b -> swizzled smem
//   Phase 2: each thread reads its row from smem (conflict-free via XOR
//            swizzle col = k ^ ((row>>1)&3): every 8-lane LDS.128 phase
//            touches all 32 banks exactly once), 256 FFMAs in registers
//   Phase 3: row -> swizzled smem -> fully-coalesced float4 global stores
// All global traffic is contiguous (4 lines per warp-instruction), removing
// the L1tex wavefront amplification of the 64B-stride AoS pattern.
// ---------------------------------------------------------------------------
__global__ void __launch_bounds__(256)
clifford_mul_kernel(const float4* __restrict__ a4,
                    const float4* __restrict__ b4,
                    float4* __restrict__ o4,
                    int n_rows) {
    constexpr cl::Tables TBL = cl::make_tables();

    __shared__ float4 sa[1024];
    __shared__ float4 sb[1024];

    const int t = threadIdx.x;                       // 0..255
    const size_t block_base = (size_t)blockIdx.x * 1024;  // float4 units
    const size_t n4 = (size_t)n_rows * 4;

    // ---- Phase 1: coalesced load -> swizzled smem ----
#pragma unroll
    for (int p = 0; p < 4; ++p) {
        const int f = t + 256 * p;                   // 0..1023
        const int row = f >> 2;
        const int k = f & 3;
        const int col = k ^ ((row >> 1) & 3);
        const size_t g = block_base + f;
        if (g < n4) {
            sa[row * 4 + col] = a4[g];
            sb[row * 4 + col] = b4[g];
        }
    }
    __syncthreads();

    // ---- Phase 2: per-thread row compute ----
    float av[16], bv[16];
#pragma unroll
    for (int k = 0; k < 4; ++k) {
        const int col = k ^ ((t >> 1) & 3);
        float4 va = sa[t * 4 + col];
        av[4 * k + 0] = va.x; av[4 * k + 1] = va.y;
        av[4 * k + 2] = va.z; av[4 * k + 3] = va.w;
        float4 vb = sb[t * 4 + col];
        bv[4 * k + 0] = vb.x; bv[4 * k + 1] = vb.y;
        bv[4 * k + 2] = vb.z; bv[4 * k + 3] = vb.w;
    }

    float acc[16];
#pragma unroll
    for (int c = 0; c < 16; ++c) acc[c] = 0.0f;

#pragma unroll
    for (int i = 0; i < 16; ++i) {
#pragma unroll
        for (int j = 0; j < 16; ++j) {
            // Compile-time sign; negation is a free FFMA operand modifier.
            if (TBL.sign[i][j] > 0.0f) {
                acc[i ^ j] = fmaf(av[i], bv[j], acc[i ^ j]);
            } else {
                acc[i ^ j] = fmaf(-av[i], bv[j], acc[i ^ j]);
            }
        }
    }
    __syncthreads();   // all smem reads done; safe to reuse sa for output

    // ---- Phase 3: row -> swizzled smem -> coalesced store ----
#pragma unroll
    for (int k = 0; k < 4; ++k) {
        const int col = k ^ ((t >> 1) & 3);
        float4 v;
        v.x = fminf(fmaxf(acc[4 * k + 0], -1000.0f), 1000.0f);
        v.y = fminf(fmaxf(acc[4 * k + 1], -1000.0f), 1000.0f);
        v.z = fminf(fmaxf(acc[4 * k + 2], -1000.0f), 1000.0f);
        v.w = fminf(fmaxf(acc[4 * k + 3], -1000.0f), 1000.0f);
        sa[t * 4 + col] = v;
    }
    __syncthreads();

#pragma unroll
    for (int p = 0; p < 4; ++p) {
        const int f = t + 256 * p;
        const int row = f >> 2;
        const int k = f & 3;
        const int col = k ^ ((row >> 1) & 3);
        const size_t g = block_base + f;
        if (g < n4) {
            o4[g] = sa[row * 4 + col];
        }
    }
}

extern "C" void kernel_launch(void* const* d_in, const int* in_sizes, int n_in,
                              void* d_out, int out_size) {
    const float4* a = (const float4*)d_in[0];
    const float4* b = (const float4*)d_in[1];
    float4* out = (float4*)d_out;

    const int n_rows = in_sizes[0] / 16;  // 1,048,576
    const int threads = 256;
    const int rows_per_block = 256;
    const int blocks = (n_rows + rows_per_block - 1) / rows_per_block;  // 4096

    clifford_mul_kernel<<<blocks, threads>>>(a, b, out, n_rows);
}

// round 5
// speedup vs baseline: 1.0564x; 1.0009x over previous
#include <cuda_runtime.h>
#include <cstdint>

// ---------------------------------------------------------------------------
// Compile-time Cayley sign table for Cl(3,1,0), DIM = 16.
// Mirrors the reference Python blade_sign() exactly.
// For r=0 the product blade is always c = i ^ j and sign is +/-1.
// ---------------------------------------------------------------------------
namespace cl {

constexpr int NGEN = 4;
constexpr int DIM  = 16;
constexpr int PP   = 3;   // first 3 generators square to +1, 4th to -1

__host__ __device__ constexpr float metric_of(int b) {
    return b < PP ? 1.0f : -1.0f;
}

__host__ __device__ constexpr float blade_sign_of(int a_idx, int b_idx) {
    int result[NGEN] = {0, 0, 0, 0};
    int len = 0;
    for (int i = 0; i < NGEN; ++i)
        if ((a_idx >> i) & 1) result[len++] = i;
    float sign = 1.0f;
    for (int b = 0; b < NGEN; ++b) {
        if (!((b_idx >> b) & 1)) continue;
        int swaps = 0;
        bool removed = false;
        for (int i = len - 1; i >= 0; --i) {
            if (result[i] < b) break;
            if (result[i] == b) {
                sign *= metric_of(b);
                if (swaps & 1) sign = -sign;
                for (int k = i; k < len - 1; ++k) result[k] = result[k + 1];
                --len;
                removed = true;
                break;
            }
            ++swaps;
        }
        if (!removed) {
            if (swaps & 1) sign = -sign;
            int ins = len - swaps;
            for (int k = len; k > ins; --k) result[k] = result[k - 1];
            result[ins] = b;
            ++len;
        }
    }
    return sign;
}

struct Tables { float sign[DIM][DIM]; };

__host__ __device__ constexpr Tables make_tables() {
    Tables t{};
    for (int i = 0; i < DIM; ++i)
        for (int j = 0; j < DIM; ++j)
            t.sign[i][j] = blade_sign_of(i, j);
    return t;
}

} // namespace cl

// ---------------------------------------------------------------------------
// Smem-staged, register-lean kernel: block of 256 threads = 256 rows.
//   Phase 1: fully-coalesced float4 global loads of a,b -> swizzled smem
//   Phase 2: av row fully in registers; bv STREAMED from smem one float4
//            per k-step (cuts live regs ~62 -> ~45 so 5 blocks/SM fit)
//   Phase 3: row -> swizzled smem -> fully-coalesced float4 global stores
// XOR swizzle col = k ^ ((row>>1)&3) keeps every 8-lane LDS/STS.128 phase
// touching all 32 banks exactly once (conflict-free both directions).
// __launch_bounds__(256, 5): target <=51 regs, 1280 threads/SM resident.
// ---------------------------------------------------------------------------
__global__ void __launch_bounds__(256, 5)
clifford_mul_kernel(const float4* __restrict__ a4,
                    const float4* __restrict__ b4,
                    float4* __restrict__ o4,
                    int n_rows) {
    constexpr cl::Tables TBL = cl::make_tables();

    __shared__ float4 sa[1024];
    __shared__ float4 sb[1024];

    const int t = threadIdx.x;                            // 0..255
    const size_t block_base = (size_t)blockIdx.x * 1024;  // float4 units
    const size_t n4 = (size_t)n_rows * 4;

    // ---- Phase 1: coalesced load -> swizzled smem ----
#pragma unroll
    for (int p = 0; p < 4; ++p) {
        const int f = t + 256 * p;                        // 0..1023
        const int row = f >> 2;
        const int k = f & 3;
        const int col = k ^ ((row >> 1) & 3);
        const size_t g = block_base + f;
        if (g < n4) {
            sa[row * 4 + col] = a4[g];
            sb[row * 4 + col] = b4[g];
        }
    }
    __syncthreads();

    // ---- Phase 2: per-thread row compute, bv streamed from smem ----
    float av[16];
#pragma unroll
    for (int k = 0; k < 4; ++k) {
        const int col = k ^ ((t >> 1) & 3);
        float4 va = sa[t * 4 + col];
        av[4 * k + 0] = va.x; av[4 * k + 1] = va.y;
        av[4 * k + 2] = va.z; av[4 * k + 3] = va.w;
    }

    float acc[16];
#pragma unroll
    for (int c = 0; c < 16; ++c) acc[c] = 0.0f;

#pragma unroll
    for (int k = 0; k < 4; ++k) {
        const int col = k ^ ((t >> 1) & 3);
        const float4 vb = sb[t * 4 + col];
        const float bvk[4] = {vb.x, vb.y, vb.z, vb.w};
#pragma unroll
        for (int jj = 0; jj < 4; ++jj) {
            const int j = 4 * k + jj;
#pragma unroll
            for (int i = 0; i < 16; ++i) {
                // Compile-time sign; negation is a free FFMA modifier.
                if (TBL.sign[i][j] > 0.0f) {
                    acc[i ^ j] = fmaf(av[i], bvk[jj], acc[i ^ j]);
                } else {
                    acc[i ^ j] = fmaf(-av[i], bvk[jj], acc[i ^ j]);
                }
            }
        }
    }
    __syncthreads();   // all smem reads done; safe to reuse sa for output

    // ---- Phase 3: row -> swizzled smem -> coalesced store ----
#pragma unroll
    for (int k = 0; k < 4; ++k) {
        const int col = k ^ ((t >> 1) & 3);
        float4 v;
        v.x = fminf(fmaxf(acc[4 * k + 0], -1000.0f), 1000.0f);
        v.y = fminf(fmaxf(acc[4 * k + 1], -1000.0f), 1000.0f);
        v.z = fminf(fmaxf(acc[4 * k + 2], -1000.0f), 1000.0f);
        v.w = fminf(fmaxf(acc[4 * k + 3], -1000.0f), 1000.0f);
        sa[t * 4 + col] = v;
    }
    __syncthreads();

#pragma unroll
    for (int p = 0; p < 4; ++p) {
        const int f = t + 256 * p;
        const int row = f >> 2;
        const int k = f & 3;
        const int col = k ^ ((row >> 1) & 3);
        const size_t g = block_base + f;
        if (g < n4) {
            o4[g] = sa[row * 4 + col];
        }
    }
}

extern "C" void kernel_launch(void* const* d_in, const int* in_sizes, int n_in,
                              void* d_out, int out_size) {
    const float4* a = (const float4*)d_in[0];
    const float4* b = (const float4*)d_in[1];
    float4* out = (float4*)d_out;

    const int n_rows = in_sizes[0] / 16;  // 1,048,576
    const int threads = 256;
    const int rows_per_block = 256;
    const int blocks = (n_rows + rows_per_block - 1) / rows_per_block;  // 4096

    clifford_mul_kernel<<<blocks, threads>>>(a, b, out, n_rows);
}

// round 6
// speedup vs baseline: 1.1310x; 1.0706x over previous
#include <cuda_runtime.h>
#include <cstdint>

// ---------------------------------------------------------------------------
// Compile-time Cayley sign table for Cl(3,1,0), DIM = 16.
// Mirrors the reference Python blade_sign() exactly.
// For r=0 the product blade is always c = i ^ j and sign is +/-1.
// ---------------------------------------------------------------------------
namespace cl {

constexpr int NGEN = 4;
constexpr int DIM  = 16;
constexpr int PP   = 3;   // first 3 generators square to +1, 4th to -1

__host__ __device__ constexpr float metric_of(int b) {
    return b < PP ? 1.0f : -1.0f;
}

__host__ __device__ constexpr float blade_sign_of(int a_idx, int b_idx) {
    int result[NGEN] = {0, 0, 0, 0};
    int len = 0;
    for (int i = 0; i < NGEN; ++i)
        if ((a_idx >> i) & 1) result[len++] = i;
    float sign = 1.0f;
    for (int b = 0; b < NGEN; ++b) {
        if (!((b_idx >> b) & 1)) continue;
        int swaps = 0;
        bool removed = false;
        for (int i = len - 1; i >= 0; --i) {
            if (result[i] < b) break;
            if (result[i] == b) {
                sign *= metric_of(b);
                if (swaps & 1) sign = -sign;
                for (int k = i; k < len - 1; ++k) result[k] = result[k + 1];
                --len;
                removed = true;
                break;
            }
            ++swaps;
        }
        if (!removed) {
            if (swaps & 1) sign = -sign;
            int ins = len - swaps;
            for (int k = len; k > ins; --k) result[k] = result[k - 1];
            result[ins] = b;
            ++len;
        }
    }
    return sign;
}

struct Tables { float sign[DIM][DIM]; };

__host__ __device__ constexpr Tables make_tables() {
    Tables t{};
    for (int i = 0; i < DIM; ++i)
        for (int j = 0; j < DIM; ++j)
            t.sign[i][j] = blade_sign_of(i, j);
    return t;
}

} // namespace cl

// ---------------------------------------------------------------------------
// Blackwell 256-bit global memory ops (sm_100+): v8.f32 load / store.
// Row base is 64B-aligned so 32B alignment requirement is satisfied.
// ---------------------------------------------------------------------------
__device__ __forceinline__ void ldg256(const float* __restrict__ p, float* v) {
    asm volatile(
        "ld.global.nc.v8.f32 {%0,%1,%2,%3,%4,%5,%6,%7}, [%8];"
        : "=f"(v[0]), "=f"(v[1]), "=f"(v[2]), "=f"(v[3]),
          "=f"(v[4]), "=f"(v[5]), "=f"(v[6]), "=f"(v[7])
        : "l"(p));
}

__device__ __forceinline__ void stg256(float* __restrict__ p, const float* v) {
    asm volatile(
        "st.global.v8.f32 [%0], {%1,%2,%3,%4,%5,%6,%7,%8};"
        :: "l"(p),
           "f"(v[0]), "f"(v[1]), "f"(v[2]), "f"(v[3]),
           "f"(v[4]), "f"(v[5]), "f"(v[6]), "f"(v[7])
        : "memory");
}

// ---------------------------------------------------------------------------
// Direct kernel (best structure so far): one thread = one row.
//   2x LDG.256 for a, 2x LDG.256 for b   (was 4+4 LDG.128)
//   256 FFMAs into 16 register accumulators (acc index folds: i^j)
//   2x STG.256 out, clamped to [-1000, 1000]
// Halves memory-instruction count vs float4 version; pure HBM streaming.
// ---------------------------------------------------------------------------
__global__ void __launch_bounds__(256)
clifford_mul_kernel(const float* __restrict__ a,
                    const float* __restrict__ b,
                    float* __restrict__ out,
                    int n_rows) {
    constexpr cl::Tables TBL = cl::make_tables();

    const int row = blockIdx.x * blockDim.x + threadIdx.x;
    if (row >= n_rows) return;

    const size_t base = (size_t)row * 16;

    float av[16], bv[16];
    ldg256(a + base, av);
    ldg256(a + base + 8, av + 8);
    ldg256(b + base, bv);
    ldg256(b + base + 8, bv + 8);

    float acc[16];
#pragma unroll
    for (int c = 0; c < 16; ++c) acc[c] = 0.0f;

#pragma unroll
    for (int i = 0; i < 16; ++i) {
#pragma unroll
        for (int j = 0; j < 16; ++j) {
            // Compile-time constant sign after full unroll; negation is a
            // free FFMA operand modifier in SASS.
            if (TBL.sign[i][j] > 0.0f) {
                acc[i ^ j] = fmaf(av[i], bv[j], acc[i ^ j]);
            } else {
                acc[i ^ j] = fmaf(-av[i], bv[j], acc[i ^ j]);
            }
        }
    }

    float res[16];
#pragma unroll
    for (int c = 0; c < 16; ++c)
        res[c] = fminf(fmaxf(acc[c], -1000.0f), 1000.0f);

    stg256(out + base, res);
    stg256(out + base + 8, res + 8);
}

extern "C" void kernel_launch(void* const* d_in, const int* in_sizes, int n_in,
                              void* d_out, int out_size) {
    const float* a = (const float*)d_in[0];
    const float* b = (const float*)d_in[1];
    float* out = (float*)d_out;

    const int n_rows = in_sizes[0] / 16;  // 1,048,576
    const int threads = 256;
    const int blocks = (n_rows + threads - 1) / threads;
    clifford_mul_kernel<<<blocks, threads>>>(a, b, out, n_rows);
}